// round 9
// baseline (speedup 1.0000x reference)
#include <cuda_runtime.h>
#include <cuda_bf16.h>
#include <cstdint>

#define B_ 16
#define P_ 16
#define I_ 16
#define L_ 64
#define D_ 128
#define F_ 128
#define C_ 1024
#define BPI 4096
#define BP 256
#define NEG (-1000000000.0f)
#define INV_SQRT_F 0.08838834764831845f

// ---------------- scratch (no allocations allowed) ----------------
__device__ float d_meanx[BPI * D_];       // (B,P,I,D) masked means
__device__ float d_WcT[D_ * 384];         // folded PIA qkv weight, transposed [d][t]
__device__ float d_bc[384];               // folded PIA qkv bias
__device__ float d_powT[D_ * F_];         // pia_out_w transposed [f][t]
__device__ float d_miwT[D_ * 384];        // mpa_in_w transposed [d][t]
__device__ float d_mowT[D_ * F_];         // mpa_out_w transposed [f][t]
__device__ float d_qiwVT[F_ * F_];        // qia_in_w rows [2F..3F) transposed [f][t]
__device__ float d_qowT[F_ * F_];         // qia_out_w transposed [f][t]
__device__ float d_meta[BP * F_];         // (B,P,F)
__device__ float d_base[B_];              // per-b score base
__device__ float d_scores[B_ * P_ * C_]; // raw candidate dots (masked in softmax)

// ---------------- Kernel A: masked mean over L (256 threads) ----------------
__global__ void k_mean(const float* __restrict__ pe, const int* __restrict__ plen) {
    int bpi = blockIdx.x;
    int len = plen[bpi];
    int warp = threadIdx.x >> 5, lane = threadIdx.x & 31;
    const float4* base = (const float4*)pe + (size_t)bpi * (L_ * 32);
    float4 acc = make_float4(0.f, 0.f, 0.f, 0.f);
    for (int l = warp; l < len; l += 8) {
        float4 v = base[l * 32 + lane];
        acc.x += v.x; acc.y += v.y; acc.z += v.z; acc.w += v.w;
    }
    __shared__ float4 sred[256];
    sred[threadIdx.x] = acc;
    __syncthreads();
    if (warp == 0) {
        float4 r = sred[lane];
        #pragma unroll
        for (int w = 1; w < 8; w++) {
            float4 v = sred[w * 32 + lane];
            r.x += v.x; r.y += v.y; r.z += v.z; r.w += v.w;
        }
        float inv = 1.0f / (float)len;
        r.x *= inv; r.y *= inv; r.z *= inv; r.w *= inv;
        ((float4*)d_meanx)[(size_t)bpi * 32 + lane] = r;
    }
}

// ---------------- Kernel B: weight fold + transposes (merged) ----------------
__global__ void k_wprep(const float* __restrict__ piw, const float* __restrict__ pib,
                        const float* __restrict__ cw, const float* __restrict__ cb,
                        const float* __restrict__ pow_, const float* __restrict__ miw,
                        const float* __restrict__ mow, const float* __restrict__ qiw,
                        const float* __restrict__ qow) {
    int t = blockIdx.x;      // 0..383
    int d = threadIdx.x;     // 0..127
    float s = 0.f;
    #pragma unroll 4
    for (int f = 0; f < F_; f++) s += piw[t * F_ + f] * cw[f * D_ + d];
    d_WcT[d * 384 + t] = s;
    d_miwT[d * 384 + t] = miw[t * F_ + d];
    if (t < F_) {
        d_powT[d * F_ + t] = pow_[t * D_ + d];
        d_mowT[d * F_ + t] = mow[t * D_ + d];
        d_qiwVT[d * F_ + t] = qiw[(size_t)(2 * F_ + t) * F_ + d];
        d_qowT[d * F_ + t] = qow[t * F_ + d];
    }
    __shared__ float sb[128];
    sb[d] = piw[t * F_ + d] * cb[d];
    __syncthreads();
    for (int off = 64; off > 0; off >>= 1) {
        if (d < off) sb[d] += sb[d + off];
        __syncthreads();
    }
    if (d == 0) d_bc[t] = pib[t] + sb[0];
}

// ---------------- Kernel C: PIA attention per (b,p), 4x4-blocked qkv ----------------
__global__ void k_pia(const float* __restrict__ pob) {
    int bp = blockIdx.x;
    int t = threadIdx.x;  // 0..383
    __shared__ float xst[128 * 20];   // x transposed [d][i], row stride 20 (16B-aligned)
    __shared__ float qs[I_ * 132], ks[I_ * 132], vs[I_ * 132];
    __shared__ float attn[I_ * I_];
    __shared__ float amean[I_];
    __shared__ float vmean[D_];

    const float* xg = d_meanx + (size_t)bp * I_ * D_;
    for (int idx = t; idx < I_ * D_; idx += 384) {
        int i = idx >> 7, d = idx & 127;
        xst[d * 20 + i] = xg[idx];
    }
    __syncthreads();

    // qkv: thread = (iquad, tquad) -> rows iquad*4..+3, outputs tquad*4..+3
    {
        int tquad = t % 96, iquad = t / 96;
        const float4* W4 = (const float4*)d_WcT;  // [d][96]
        const float4* X4 = (const float4*)xst;    // [d][5]
        float acc[16];
        #pragma unroll
        for (int k = 0; k < 16; k++) acc[k] = 0.f;
        #pragma unroll 4
        for (int d = 0; d < D_; d++) {
            float4 w = W4[d * 96 + tquad];
            float4 x = X4[d * 5 + iquad];
            acc[0]  += x.x * w.x; acc[1]  += x.x * w.y; acc[2]  += x.x * w.z; acc[3]  += x.x * w.w;
            acc[4]  += x.y * w.x; acc[5]  += x.y * w.y; acc[6]  += x.y * w.z; acc[7]  += x.y * w.w;
            acc[8]  += x.z * w.x; acc[9]  += x.z * w.y; acc[10] += x.z * w.z; acc[11] += x.z * w.w;
            acc[12] += x.w * w.x; acc[13] += x.w * w.y; acc[14] += x.w * w.z; acc[15] += x.w * w.w;
        }
        #pragma unroll
        for (int tt = 0; tt < 4; tt++) {
            int to = tquad * 4 + tt;
            float bb = d_bc[to];
            float* dst = (to < 128) ? qs : (to < 256 ? ks : vs);
            int f = to & 127;
            #pragma unroll
            for (int ii = 0; ii < 4; ii++)
                dst[(iquad * 4 + ii) * 132 + f] = acc[ii * 4 + tt] + bb;
        }
    }
    __syncthreads();

    if (t < 256) {
        int i = t >> 4, j = t & 15;
        const float4* q4 = (const float4*)(qs + i * 132);
        const float4* k4 = (const float4*)(ks + j * 132);
        float s = 0.f;
        #pragma unroll 8
        for (int f = 0; f < 32; f++) {
            float4 a = q4[f], b = k4[f];
            s += a.x * b.x + a.y * b.y + a.z * b.z + a.w * b.w;
        }
        attn[t] = s * INV_SQRT_F;
    }
    __syncthreads();
    if (t < I_) {
        float m = attn[t * 16];
        for (int j = 1; j < 16; j++) m = fmaxf(m, attn[t * 16 + j]);
        float sum = 0.f;
        for (int j = 0; j < 16; j++) { float e = __expf(attn[t * 16 + j] - m); attn[t * 16 + j] = e; sum += e; }
        float inv = 1.f / sum;
        for (int j = 0; j < 16; j++) attn[t * 16 + j] *= inv;
    }
    __syncthreads();
    if (t < I_) {
        float s = 0.f;
        for (int i = 0; i < 16; i++) s += attn[i * 16 + t];
        amean[t] = s * (1.f / 16.f);
    }
    __syncthreads();
    if (t < D_) {
        float s = 0.f;
        #pragma unroll
        for (int j = 0; j < I_; j++) s += amean[j] * vs[j * 132 + t];
        vmean[t] = s;
    }
    __syncthreads();
    if (t < F_) {
        float s = pob[t];
        #pragma unroll 8
        for (int f = 0; f < D_; f++) s += vmean[f] * d_powT[f * F_ + t];
        d_meta[(size_t)bp * F_ + t] = s;
    }
}

// ---------------- Kernel D: MPA per b + v2 + score base (4x4-blocked qkv) ----------------
__global__ void k_mpa(const float* __restrict__ mib, const float* __restrict__ mob,
                      const float* __restrict__ qib, const float* __restrict__ qob,
                      const float* __restrict__ query, const float* __restrict__ sw,
                      const float* __restrict__ sb) {
    int b = blockIdx.x;
    int t = threadIdx.x;  // 0..383
    __shared__ float xst[128 * 20];
    __shared__ float qs[I_ * 132], ks[I_ * 132], vs[I_ * 132];
    __shared__ float attn[I_ * I_];
    __shared__ float amean[I_];
    __shared__ float vmean[D_], v1s[F_], mps[F_], t1s[F_], v2s[F_];
    __shared__ float red[128];

    const float* xg = d_meta + (size_t)b * I_ * D_;
    for (int idx = t; idx < I_ * D_; idx += 384) {
        int i = idx >> 7, d = idx & 127;
        xst[d * 20 + i] = xg[idx];
    }
    __syncthreads();

    {
        int tquad = t % 96, iquad = t / 96;
        const float4* W4 = (const float4*)d_miwT;
        const float4* X4 = (const float4*)xst;
        float acc[16];
        #pragma unroll
        for (int k = 0; k < 16; k++) acc[k] = 0.f;
        #pragma unroll 4
        for (int d = 0; d < D_; d++) {
            float4 w = W4[d * 96 + tquad];
            float4 x = X4[d * 5 + iquad];
            acc[0]  += x.x * w.x; acc[1]  += x.x * w.y; acc[2]  += x.x * w.z; acc[3]  += x.x * w.w;
            acc[4]  += x.y * w.x; acc[5]  += x.y * w.y; acc[6]  += x.y * w.z; acc[7]  += x.y * w.w;
            acc[8]  += x.z * w.x; acc[9]  += x.z * w.y; acc[10] += x.z * w.z; acc[11] += x.z * w.w;
            acc[12] += x.w * w.x; acc[13] += x.w * w.y; acc[14] += x.w * w.z; acc[15] += x.w * w.w;
        }
        #pragma unroll
        for (int tt = 0; tt < 4; tt++) {
            int to = tquad * 4 + tt;
            float bb = mib[to];
            float* dst = (to < 128) ? qs : (to < 256 ? ks : vs);
            int f = to & 127;
            #pragma unroll
            for (int ii = 0; ii < 4; ii++)
                dst[(iquad * 4 + ii) * 132 + f] = acc[ii * 4 + tt] + bb;
        }
    }
    __syncthreads();

    if (t < 256) {
        int i = t >> 4, j = t & 15;
        const float4* q4 = (const float4*)(qs + i * 132);
        const float4* k4 = (const float4*)(ks + j * 132);
        float s = 0.f;
        #pragma unroll 8
        for (int f = 0; f < 32; f++) {
            float4 a = q4[f], b = k4[f];
            s += a.x * b.x + a.y * b.y + a.z * b.z + a.w * b.w;
        }
        attn[t] = s * INV_SQRT_F;
    }
    __syncthreads();
    if (t < I_) {
        float m = attn[t * 16];
        for (int j = 1; j < 16; j++) m = fmaxf(m, attn[t * 16 + j]);
        float sum = 0.f;
        for (int j = 0; j < 16; j++) { float e = __expf(attn[t * 16 + j] - m); attn[t * 16 + j] = e; sum += e; }
        float inv = 1.f / sum;
        for (int j = 0; j < 16; j++) attn[t * 16 + j] *= inv;
    }
    __syncthreads();
    if (t < I_) {
        float s = 0.f;
        for (int i = 0; i < 16; i++) s += attn[i * 16 + t];
        amean[t] = s * (1.f / 16.f);
    }
    __syncthreads();
    if (t < D_) {  // vmean and mean over P of meta (from transposed xst)
        float s = 0.f;
        #pragma unroll
        for (int j = 0; j < I_; j++) s += amean[j] * vs[j * 132 + t];
        vmean[t] = s;
        float sm = 0.f;
        #pragma unroll
        for (int i = 0; i < I_; i++) sm += xst[t * 20 + i];
        mps[t] = sm * (1.f / 16.f);
    }
    __syncthreads();
    if (t < F_) {
        float s = mob[t];
        #pragma unroll 8
        for (int f = 0; f < D_; f++) s += vmean[f] * d_mowT[f * F_ + t];
        v1s[t] = s;
        float s2 = qib[2 * F_ + t];
        #pragma unroll 8
        for (int f = 0; f < F_; f++) s2 += mps[f] * d_qiwVT[f * F_ + t];
        t1s[t] = s2;
    }
    __syncthreads();
    if (t < F_) {
        float s = qob[t];
        #pragma unroll 8
        for (int f = 0; f < F_; f++) s += t1s[f] * d_qowT[f * F_ + t];
        v2s[t] = s;
    }
    __syncthreads();
    if (t < 128) {
        red[t] = query[b * D_ + t] * sw[t] + v1s[t] * sw[D_ + t] + v2s[t] * sw[D_ + F_ + t];
    }
    __syncthreads();
    for (int off = 64; off > 0; off >>= 1) {
        if (t < off) red[t] += red[t + off];
        __syncthreads();
    }
    if (t == 0) d_base[b] = red[0] + sb[0];
}

// ---------------- Kernel F: candidate raw dots (independent of base/mask) ----------------
__global__ void k_scoredot(const float* __restrict__ cand, const float* __restrict__ sw) {
    int bp = blockIdx.x;
    int cbeg = blockIdx.y * (C_ / 4);
    int warp = threadIdx.x >> 5, lane = threadIdx.x & 31;
    __shared__ float4 ws[32];
    if (threadIdx.x < 32) ws[threadIdx.x] = ((const float4*)(sw + D_ + 2 * F_))[threadIdx.x];
    __syncthreads();
    const float4* cbase = (const float4*)cand + (size_t)bp * C_ * 32;
    float4 w = ws[lane];
    #pragma unroll 4
    for (int cc = warp; cc < C_ / 4; cc += 8) {
        int c = cbeg + cc;
        float4 v = cbase[c * 32 + lane];
        float s = v.x * w.x + v.y * w.y + v.z * w.z + v.w * w.w;
        #pragma unroll
        for (int off = 16; off; off >>= 1) s += __shfl_xor_sync(0xffffffffu, s, off);
        if (lane == 0) d_scores[(size_t)bp * C_ + c] = s;
    }
}

// ---------------- Kernel G: mask + base + softmax over P*C per b ----------------
__global__ void k_softmax(float* __restrict__ out, const int* __restrict__ clen) {
    int b = blockIdx.x;
    float* s = d_scores + (size_t)b * (P_ * C_);
    float* o = out + (size_t)b * (P_ * C_);
    int t = threadIdx.x;  // 0..1023
    __shared__ int lens[P_];
    __shared__ float red[1024];
    if (t < P_) lens[t] = clen[b * P_ + t];
    __syncthreads();
    float base = d_base[b];
    float m = -1e30f;
    for (int i = t; i < P_ * C_; i += 1024) {
        int p = i >> 10, c = i & (C_ - 1);
        float v = (c < lens[p]) ? (s[i] + base) : NEG;
        s[i] = v;
        m = fmaxf(m, v);
    }
    red[t] = m;
    __syncthreads();
    for (int off = 512; off > 0; off >>= 1) {
        if (t < off) red[t] = fmaxf(red[t], red[t + off]);
        __syncthreads();
    }
    float mx = red[0];
    __syncthreads();
    float sum = 0.f;
    for (int i = t; i < P_ * C_; i += 1024) sum += __expf(s[i] - mx);
    red[t] = sum;
    __syncthreads();
    for (int off = 512; off > 0; off >>= 1) {
        if (t < off) red[t] += red[t + off];
        __syncthreads();
    }
    float inv = 1.f / red[0];
    for (int i = t; i < P_ * C_; i += 1024) o[i] = __expf(s[i] - mx) * inv;
}

// ---------------- launch (forked graph: scoredot & wprep overlap the chain) ----------------
extern "C" void kernel_launch(void* const* d_in, const int* in_sizes, int n_in,
                              void* d_out, int out_size) {
    const float* query    = (const float*)d_in[0];
    const float* path_emb = (const float*)d_in[1];
    const int*   path_len = (const int*)d_in[2];
    const float* cand_emb = (const float*)d_in[3];
    const int*   cand_len = (const int*)d_in[4];
    const float* conv_w   = (const float*)d_in[5];
    const float* conv_b   = (const float*)d_in[6];
    const float* pia_in_w = (const float*)d_in[7];
    const float* pia_in_b = (const float*)d_in[8];
    const float* pia_out_w= (const float*)d_in[9];
    const float* pia_out_b= (const float*)d_in[10];
    const float* mpa_in_w = (const float*)d_in[11];
    const float* mpa_in_b = (const float*)d_in[12];
    const float* mpa_out_w= (const float*)d_in[13];
    const float* mpa_out_b= (const float*)d_in[14];
    const float* qia_in_w = (const float*)d_in[15];
    const float* qia_in_b = (const float*)d_in[16];
    const float* qia_out_w= (const float*)d_in[17];
    const float* qia_out_b= (const float*)d_in[18];
    const float* score_w  = (const float*)d_in[19];
    const float* score_b  = (const float*)d_in[20];
    float* out = (float*)d_out;

    static cudaStream_t s1 = nullptr, s2 = nullptr;
    static cudaEvent_t evR = nullptr, evS1 = nullptr, evS2 = nullptr;
    if (s1 == nullptr) {
        cudaStreamCreateWithFlags(&s1, cudaStreamNonBlocking);
        cudaStreamCreateWithFlags(&s2, cudaStreamNonBlocking);
        cudaEventCreateWithFlags(&evR, cudaEventDisableTiming);
        cudaEventCreateWithFlags(&evS1, cudaEventDisableTiming);
        cudaEventCreateWithFlags(&evS2, cudaEventDisableTiming);
    }

    // fork
    cudaEventRecord(evR, 0);
    cudaStreamWaitEvent(s1, evR, 0);
    cudaStreamWaitEvent(s2, evR, 0);

    // branch 1: candidate dots (134 MB stream, fully independent)
    k_scoredot<<<dim3(BP, 4), 256, 0, s1>>>(cand_emb, score_w);
    cudaEventRecord(evS1, s1);

    // branch 2: weight fold + transposes
    k_wprep<<<384, 128, 0, s2>>>(pia_in_w, pia_in_b, conv_w, conv_b,
                                 pia_out_w, mpa_in_w, mpa_out_w, qia_in_w, qia_out_w);
    cudaEventRecord(evS2, s2);

    // main chain
    k_mean<<<BPI, 256>>>(path_emb, path_len);
    cudaStreamWaitEvent(0, evS2, 0);
    k_pia<<<BP, 384>>>(pia_out_b);
    k_mpa<<<B_, 384>>>(mpa_in_b, mpa_out_b, qia_in_b, qia_out_b,
                       query, score_w, score_b);
    cudaStreamWaitEvent(0, evS1, 0);
    k_softmax<<<B_, 1024>>>(out, cand_len);
}

// round 13
// speedup vs baseline: 8.7563x; 8.7563x over previous
#include <cuda_runtime.h>
#include <cuda_bf16.h>
#include <cstdint>

#define B_ 16
#define P_ 16
#define D_ 128
#define F_ 128
#define C_ 1024
#define BP 256
#define NEG (-1000000000.0f)

// ---------------- scratch (no allocations allowed) ----------------
__device__ float d_scores[B_ * P_ * C_];  // masked candidate dots

// ---------------- Kernel 1: candidate scores (the only real memory work) ----------------
// scores[b,p,c] = cand_emb[b,p,c,:] . score_w[D+2F : D+2F+D]   for c < cand_len[b,p]
//              = NEG                                            otherwise (row not loaded)
// The per-b terms of the reference (query/v1/v2/score_b) are constant along the
// softmax axis (p*c) and cancel exactly in the per-b softmax; masked entries are
// -1e9 whose exp underflows to 0 identically with or without that constant.
//
// grid (BP, 8) x 256 threads: block = 128 candidates of one (b,p); warp per candidate,
// lane per float4 (32 x 16B = one full 512B row, perfectly coalesced).
__global__ void k_score(const float* __restrict__ cand, const int* __restrict__ clen,
                        const float* __restrict__ sw) {
    int bp = blockIdx.x;
    int cbeg = blockIdx.y * (C_ / 8);
    int warp = threadIdx.x >> 5, lane = threadIdx.x & 31;
    __shared__ float4 ws[32];
    if (threadIdx.x < 32) ws[threadIdx.x] = ((const float4*)(sw + D_ + 2 * F_))[threadIdx.x];
    int len = clen[bp];
    __syncthreads();
    float4 w = ws[lane];
    const float4* cbase = (const float4*)cand + (size_t)bp * C_ * 32;
    float* srow = d_scores + (size_t)bp * C_;
    #pragma unroll 4
    for (int cc = warp; cc < C_ / 8; cc += 8) {
        int c = cbeg + cc;
        if (c < len) {
            float4 v = cbase[c * 32 + lane];
            float s = v.x * w.x + v.y * w.y + v.z * w.z + v.w * w.w;
            #pragma unroll
            for (int off = 16; off; off >>= 1) s += __shfl_xor_sync(0xffffffffu, s, off);
            if (lane == 0) srow[c] = s;
        } else if (lane == 0) {
            srow[c] = NEG;
        }
    }
}

// ---------------- Kernel 2: softmax over P*C per b (single-read, register-resident) ----------------
__global__ void k_softmax(float* __restrict__ out) {
    int b = blockIdx.x;
    int t = threadIdx.x;  // 0..1023
    const float* s = d_scores + (size_t)b * (P_ * C_);
    float* o = out + (size_t)b * (P_ * C_);
    __shared__ float red[32];

    float v[16];
    float m = -1e30f;
    #pragma unroll
    for (int r = 0; r < 16; r++) {
        v[r] = s[t + r * 1024];
        m = fmaxf(m, v[r]);
    }
    // block max: warp shfl then cross-warp smem
    #pragma unroll
    for (int off = 16; off; off >>= 1) m = fmaxf(m, __shfl_xor_sync(0xffffffffu, m, off));
    if ((t & 31) == 0) red[t >> 5] = m;
    __syncthreads();
    if (t < 32) {
        float mm = red[t];
        #pragma unroll
        for (int off = 16; off; off >>= 1) mm = fmaxf(mm, __shfl_xor_sync(0xffffffffu, mm, off));
        red[t] = mm;
    }
    __syncthreads();
    float mx = red[0];
    __syncthreads();

    float sum = 0.f;
    #pragma unroll
    for (int r = 0; r < 16; r++) {
        v[r] = __expf(v[r] - mx);
        sum += v[r];
    }
    #pragma unroll
    for (int off = 16; off; off >>= 1) sum += __shfl_xor_sync(0xffffffffu, sum, off);
    if ((t & 31) == 0) red[t >> 5] = sum;
    __syncthreads();
    if (t < 32) {
        float ss = red[t];
        #pragma unroll
        for (int off = 16; off; off >>= 1) ss += __shfl_xor_sync(0xffffffffu, ss, off);
        red[t] = ss;
    }
    __syncthreads();
    float inv = 1.f / red[0];

    #pragma unroll
    for (int r = 0; r < 16; r++) o[t + r * 1024] = v[r] * inv;
}

// ---------------- launch ----------------
extern "C" void kernel_launch(void* const* d_in, const int* in_sizes, int n_in,
                              void* d_out, int out_size) {
    const float* cand_emb = (const float*)d_in[3];
    const int*   cand_len = (const int*)d_in[4];
    const float* score_w  = (const float*)d_in[19];
    float* out = (float*)d_out;

    k_score<<<dim3(BP, 8), 256>>>(cand_emb, cand_len, score_w);
    k_softmax<<<B_, 1024>>>(out);
}